// round 14
// baseline (speedup 1.0000x reference)
#include <cuda_runtime.h>
#include <cstdint>

#define N_ 50000
#define K_ 32
#define D_ 128
#define EPS_ 1e-12f
#define WARPS_PER_BLOCK 8
#define THREADS_ (WARPS_PER_BLOCK * 32)
#define ROWS_PER_WARP 2
#define NBLOCKS_ (N_ / (WARPS_PER_BLOCK * ROWS_PER_WARP))   // 3125
#define PREP_BLOCKS_ ((N_ + WARPS_PER_BLOCK - 1) / WARPS_PER_BLOCK)
#define ROWB_ 384   // packed row: 256B hi-plane + 128B lo-plane

__device__ uint8_t  g_pack[(size_t)N_ * ROWB_];   // 19.2 MB
__device__ double   g_block_partials[NBLOCKS_];
__device__ unsigned g_ticket = 0;                 // returns to 0 each run (graph-replay safe)

// Warp-per-row prep: round fp32 to 24 bits, store [hi16 x128 | lo8 x128] packed row.
__global__ __launch_bounds__(THREADS_)
void snl_prep_kernel(const float* __restrict__ emb) {
    const int warp = threadIdx.x >> 5;
    const int lane = threadIdx.x & 31;
    const int i = blockIdx.x * WARPS_PER_BLOCK + warp;

    const uint4 y = reinterpret_cast<const uint4*>(emb + (size_t)i * D_)[lane];
    const unsigned r0 = y.x + 0x80u, r1 = y.y + 0x80u;
    const unsigned r2 = y.z + 0x80u, r3 = y.w + 0x80u;

    ushort4 h;
    h.x = (unsigned short)(r0 >> 16); h.y = (unsigned short)(r1 >> 16);
    h.z = (unsigned short)(r2 >> 16); h.w = (unsigned short)(r3 >> 16);
    uchar4 l;
    l.x = (unsigned char)(r0 >> 8); l.y = (unsigned char)(r1 >> 8);
    l.z = (unsigned char)(r2 >> 8); l.w = (unsigned char)(r3 >> 8);

    uint8_t* row = g_pack + (size_t)i * ROWB_;
    *reinterpret_cast<ushort4*>(row + 8 * lane) = h;        // hi plane [0,256)
    *reinterpret_cast<uchar4*>(row + 256 + 4 * lane) = l;   // lo plane [256,384)
}

__global__ __launch_bounds__(THREADS_, 4)
void snl_main_kernel(const float* __restrict__ emb,
                     const float* __restrict__ p,
                     const int* __restrict__ anchor,
                     float* __restrict__ out /* [0]=loss, [1..]=q */) {
    __shared__ double loss_s[WARPS_PER_BLOCK];
    __shared__ double red_s[THREADS_];
    __shared__ bool   is_last;

    const int warp = threadIdx.x >> 5;
    const int lane = threadIdx.x & 31;
    const int iA = (blockIdx.x * WARPS_PER_BLOCK + warp) * ROWS_PER_WARP;
    const int iB = iA + 1;
    float* __restrict__ out_q = out + 1;

    // anchor owned by lane l after the fold (pure lane function — hoist p loads)
    const int acol = 8 * (lane & 3) + 4 * ((lane >> 2) & 1)
                   + 2 * ((lane >> 3) & 1) + ((lane >> 4) & 1);

    const int jA = anchor[(size_t)iA * K_ + lane];
    const int jB = anchor[(size_t)iB * K_ + lane];
    const float pvA = p[(size_t)iA * K_ + acol];
    const float pvB = p[(size_t)iB * K_ + acol];

    const float4 aA = reinterpret_cast<const float4*>(emb + (size_t)iA * D_)[lane];
    const float4 aB = reinterpret_cast<const float4*>(emb + (size_t)iB * D_)[lane];

    const bool hi16 = (lane & 16) != 0;
    const bool hi8  = (lane & 8) != 0;
    const bool hi4  = (lane & 4) != 0;

    auto fold = [&](float lo_v, float hi_v, bool up, int s) -> float {
        const float send = up ? lo_v : hi_v;
        return (up ? hi_v : lo_v) + __shfl_xor_sync(0xffffffffu, send, s);
    };

    // one 8-anchor group for one row: batch loads -> decode -> fold
    auto group = [&](int jm, const float4& a, int g) -> float {
        uint2    hw[8];
        unsigned lw[8];
        #pragma unroll
        for (int h = 0; h < 8; h++) {
            const int jr = __shfl_sync(0xffffffffu, jm, 8 * g + h);
            const uint8_t* row = g_pack + (size_t)jr * ROWB_;
            hw[h] = *reinterpret_cast<const uint2*>(row + 8 * lane);
            lw[h] = *reinterpret_cast<const unsigned*>(row + 256 + 4 * lane);
        }
        float pp[8];
        #pragma unroll
        for (int h = 0; h < 8; h++) {
            const float bx = __uint_as_float(__byte_perm(hw[h].x, lw[h], 0x1044));
            const float by = __uint_as_float(__byte_perm(hw[h].x, lw[h], 0x3255));
            const float bz = __uint_as_float(__byte_perm(hw[h].y, lw[h], 0x1066));
            const float bw = __uint_as_float(__byte_perm(hw[h].y, lw[h], 0x3277));
            const float dx = a.x - bx, dy = a.y - by, dz = a.z - bz, dw = a.w - bw;
            float pr = dx * dx;
            pr = fmaf(dy, dy, pr);
            pr = fmaf(dz, dz, pr);
            pr = fmaf(dw, dw, pr);
            pp[h] = pr;
        }
        float u[4];
        #pragma unroll
        for (int h = 0; h < 4; h++)
            u[h] = fold(pp[2 * h], pp[2 * h + 1], hi16, 16);   // idx bit0 = b16
        const float v0 = fold(u[0], u[1], hi8, 8);             // idx bit1 = b8
        const float v1 = fold(u[2], u[3], hi8, 8);
        return fold(v0, v1, hi4, 4);                           // idx bit2 = b4
    };

    // interleaved: row A's fold tail overlaps row B's loads/decode
    float wA[K_ / 8], wB[K_ / 8];
    #pragma unroll
    for (int g = 0; g < K_ / 8; g++) {
        wA[g] = group(jA, aA, g);
        wB[g] = group(jB, aB, g);
    }

    // recursive halving on 4 values for both rows (independent -> ILP)
    #pragma unroll
    for (int s = 2; s >= 1; s >>= 1) {
        const bool upper = (lane & s) != 0;
        #pragma unroll
        for (int k = 0; k < s; k++) {
            const float sA = upper ? wA[k] : wA[k + s];
            const float sB = upper ? wB[k] : wB[k + s];
            const float rA = __shfl_xor_sync(0xffffffffu, sA, s);
            const float rB = __shfl_xor_sync(0xffffffffu, sB, s);
            wA[k] = (upper ? wA[k + s] : wA[k]) + rA;
            wB[k] = (upper ? wB[k + s] : wB[k]) + rB;
        }
    }

    // softmax over the 32 lanes for both rows (interleaved, independent chains)
    const float scA = -wA[0];
    const float scB = -wB[0];
    float mA = scA, mB = scB;
    #pragma unroll
    for (int o = 16; o; o >>= 1) {
        mA = fmaxf(mA, __shfl_xor_sync(0xffffffffu, mA, o));
        mB = fmaxf(mB, __shfl_xor_sync(0xffffffffu, mB, o));
    }
    float sumA = __expf(scA - mA);
    float sumB = __expf(scB - mB);
    #pragma unroll
    for (int o = 16; o; o >>= 1) {
        sumA += __shfl_xor_sync(0xffffffffu, sumA, o);
        sumB += __shfl_xor_sync(0xffffffffu, sumB, o);
    }
    const float logqA = scA - (mA + __logf(sumA));
    const float logqB = scB - (mB + __logf(sumB));

    out_q[(size_t)iA * K_ + acol] = __expf(logqA);
    out_q[(size_t)iB * K_ + acol] = __expf(logqB);

    float contrib = pvA * (__logf(pvA + EPS_) - logqA)
                  + pvB * (__logf(pvB + EPS_) - logqB);
    #pragma unroll
    for (int o = 16; o; o >>= 1) contrib += __shfl_xor_sync(0xffffffffu, contrib, o);
    if (lane == 0) loss_s[warp] = (double)contrib;
    __syncthreads();

    if (threadIdx.x == 0) {
        double blk = 0.0;
        #pragma unroll
        for (int w2 = 0; w2 < WARPS_PER_BLOCK; w2++) blk += loss_s[w2];
        g_block_partials[blockIdx.x] = blk;
        __threadfence();
        unsigned t = atomicAdd(&g_ticket, 1u);
        is_last = (t == (unsigned)(NBLOCKS_ - 1));
    }
    __syncthreads();

    if (is_last) {
        __threadfence();
        double acc = 0.0;
        for (int b = threadIdx.x; b < NBLOCKS_; b += THREADS_)
            acc += g_block_partials[b];
        red_s[threadIdx.x] = acc;
        __syncthreads();
        #pragma unroll
        for (int o = THREADS_ / 2; o; o >>= 1) {
            if (threadIdx.x < o) red_s[threadIdx.x] += red_s[threadIdx.x + o];
            __syncthreads();
        }
        if (threadIdx.x == 0) {
            out[0] = (float)(red_s[0] / (double)N_);
            g_ticket = 0;
        }
    }
}

extern "C" void kernel_launch(void* const* d_in, const int* in_sizes, int n_in,
                              void* d_out, int out_size) {
    const float* emb    = (const float*)d_in[0];  // output_embedding [N, D] f32
    const float* p      = (const float*)d_in[1];  // input_similarity [N, K] f32
    const int*   anchor = (const int*)d_in[2];    // anchor_idx [N, K] int32
    float* out = (float*)d_out;                   // [0]=loss, [1..]=q row-major

    snl_prep_kernel<<<PREP_BLOCKS_, THREADS_>>>(emb);
    snl_main_kernel<<<NBLOCKS_, THREADS_>>>(emb, p, anchor, out);
}

// round 15
// speedup vs baseline: 1.5462x; 1.5462x over previous
#include <cuda_runtime.h>
#include <cstdint>

#define N_ 50000
#define K_ 32
#define D_ 128
#define EPS_ 1e-12f
#define WARPS_PER_BLOCK 8
#define THREADS_ (WARPS_PER_BLOCK * 32)
#define NBLOCKS_ ((N_ + WARPS_PER_BLOCK - 1) / WARPS_PER_BLOCK)   // 6250
#define ROWB_ 384   // packed row: 256B hi-plane + 128B lo-plane

__device__ uint8_t  g_pack[(size_t)N_ * ROWB_];   // 19.2 MB
__device__ double   g_block_partials[NBLOCKS_];
__device__ unsigned g_ticket = 0;                 // returns to 0 each run (graph-replay safe)

// Warp-per-row prep: round fp32 to 24 bits, store [hi16 x128 | lo8 x128] packed row.
__global__ __launch_bounds__(THREADS_)
void snl_prep_kernel(const float* __restrict__ emb) {
    const int warp = threadIdx.x >> 5;
    const int lane = threadIdx.x & 31;
    const int i = blockIdx.x * WARPS_PER_BLOCK + warp;

    const uint4 y = reinterpret_cast<const uint4*>(emb + (size_t)i * D_)[lane];
    const unsigned r0 = y.x + 0x80u, r1 = y.y + 0x80u;
    const unsigned r2 = y.z + 0x80u, r3 = y.w + 0x80u;

    ushort4 h;
    h.x = (unsigned short)(r0 >> 16); h.y = (unsigned short)(r1 >> 16);
    h.z = (unsigned short)(r2 >> 16); h.w = (unsigned short)(r3 >> 16);
    uchar4 l;
    l.x = (unsigned char)(r0 >> 8); l.y = (unsigned char)(r1 >> 8);
    l.z = (unsigned char)(r2 >> 8); l.w = (unsigned char)(r3 >> 8);

    uint8_t* row = g_pack + (size_t)i * ROWB_;
    *reinterpret_cast<ushort4*>(row + 8 * lane) = h;        // hi plane [0,256)
    *reinterpret_cast<uchar4*>(row + 256 + 4 * lane) = l;   // lo plane [256,384)
}

__global__ __launch_bounds__(THREADS_, 5)
void snl_main_kernel(const float* __restrict__ emb,
                     const float* __restrict__ p,
                     const int* __restrict__ anchor,
                     float* __restrict__ out /* [0]=loss, [1..]=q */) {
    __shared__ double loss_s[WARPS_PER_BLOCK];
    __shared__ double red_s[THREADS_];
    __shared__ bool   is_last;

    const int warp = threadIdx.x >> 5;
    const int lane = threadIdx.x & 31;
    const int i = blockIdx.x * WARPS_PER_BLOCK + warp;   // 6250*8 == 50000 exactly
    float* __restrict__ out_q = out + 1;

    const int j_mine = anchor[(size_t)i * K_ + lane];    // lane k owns anchor k

    // anchor owned by lane l after the folds (pure lane function — hoist p load)
    const int acol = 4 * (lane & 7) + 2 * ((lane >> 3) & 1) + ((lane >> 4) & 1);
    const float pv = p[(size_t)i * K_ + acol];

    // yi exact: lane t holds dims [4t, 4t+4)
    const float4 a = reinterpret_cast<const float4*>(emb + (size_t)i * D_)[lane];

    const bool hi16 = (lane & 16) != 0;
    const bool hi8  = (lane & 8) != 0;

    auto fold = [&](float lo_v, float hi_v, bool up, int s) -> float {
        const float send = up ? lo_v : hi_v;
        return (up ? hi_v : lo_v) + __shfl_xor_sync(0xffffffffu, send, s);
    };

    // load the 4 anchors of group g into a register buffer (uniform addresses)
    auto loadgrp = [&](int g, uint2* hw, unsigned* lw) {
        #pragma unroll
        for (int h = 0; h < 4; h++) {
            const int jr = __shfl_sync(0xffffffffu, j_mine, 4 * g + h);
            const uint8_t* row = g_pack + (size_t)jr * ROWB_;
            hw[h] = *reinterpret_cast<const uint2*>(row + 8 * lane);
            lw[h] = *reinterpret_cast<const unsigned*>(row + 256 + 4 * lane);
        }
    };

    // decode 4 anchors and fold to one register (b16 pair-folds, then b8)
    auto decode_fold = [&](const uint2* hw, const unsigned* lw) -> float {
        float pp[4];
        #pragma unroll
        for (int h = 0; h < 4; h++) {
            // fp32 bytes [b3 b2 b1 b0] = [hiB1, hiB0, lo8, junk]
            const float bx = __uint_as_float(__byte_perm(hw[h].x, lw[h], 0x1044));
            const float by = __uint_as_float(__byte_perm(hw[h].x, lw[h], 0x3255));
            const float bz = __uint_as_float(__byte_perm(hw[h].y, lw[h], 0x1066));
            const float bw = __uint_as_float(__byte_perm(hw[h].y, lw[h], 0x3277));
            const float dx = a.x - bx, dy = a.y - by, dz = a.z - bz, dw = a.w - bw;
            float pr = dx * dx;
            pr = fmaf(dy, dy, pr);
            pr = fmaf(dz, dz, pr);
            pr = fmaf(dw, dw, pr);
            pp[h] = pr;
        }
        const float u0 = fold(pp[0], pp[1], hi16, 16);   // idx bit0 = b16
        const float u1 = fold(pp[2], pp[3], hi16, 16);
        return fold(u0, u1, hi8, 8);                     // idx bit1 = b8
    };

    // Software-pipelined group loop (depth 2): group g+1's loads issue
    // BEFORE group g's decode+fold, hiding the fold-tree latency.
    float w[K_ / 4];
    uint2    hwb[2][4];
    unsigned lwb[2][4];
    loadgrp(0, hwb[0], lwb[0]);
    #pragma unroll
    for (int g = 0; g < K_ / 4; g++) {
        if (g < K_ / 4 - 1)
            loadgrp(g + 1, hwb[(g + 1) & 1], lwb[(g + 1) & 1]);
        w[g] = decode_fold(hwb[g & 1], lwb[g & 1]);
    }

    // Recursive halving on 8 values: 7 shuffles; lane l ends with anchor acol(l).
    #pragma unroll
    for (int s = 4; s >= 1; s >>= 1) {
        const bool upper = (lane & s) != 0;
        #pragma unroll
        for (int k = 0; k < s; k++) {
            const float send = upper ? w[k] : w[k + s];
            const float recv = __shfl_xor_sync(0xffffffffu, send, s);
            w[k] = (upper ? w[k + s] : w[k]) + recv;
        }
    }

    // softmax over the 32 lanes of s = -d2
    const float sc = -w[0];
    float m = sc;
    #pragma unroll
    for (int o = 16; o; o >>= 1) m = fmaxf(m, __shfl_xor_sync(0xffffffffu, m, o));
    const float e = __expf(sc - m);
    float sum = e;
    #pragma unroll
    for (int o = 16; o; o >>= 1) sum += __shfl_xor_sync(0xffffffffu, sum, o);
    const float lse = m + __logf(sum);
    const float logq = sc - lse;
    const float q = __expf(logq);

    out_q[(size_t)i * K_ + acol] = q;

    float contrib = pv * (__logf(pv + EPS_) - logq);
    #pragma unroll
    for (int o = 16; o; o >>= 1) contrib += __shfl_xor_sync(0xffffffffu, contrib, o);
    if (lane == 0) loss_s[warp] = (double)contrib;
    __syncthreads();

    if (threadIdx.x == 0) {
        double blk = 0.0;
        #pragma unroll
        for (int w2 = 0; w2 < WARPS_PER_BLOCK; w2++) blk += loss_s[w2];
        g_block_partials[blockIdx.x] = blk;
        __threadfence();
        unsigned t = atomicAdd(&g_ticket, 1u);
        is_last = (t == (unsigned)(NBLOCKS_ - 1));
    }
    __syncthreads();

    if (is_last) {
        __threadfence();
        double acc = 0.0;
        for (int b = threadIdx.x; b < NBLOCKS_; b += THREADS_)
            acc += g_block_partials[b];
        red_s[threadIdx.x] = acc;
        __syncthreads();
        #pragma unroll
        for (int o = THREADS_ / 2; o; o >>= 1) {
            if (threadIdx.x < o) red_s[threadIdx.x] += red_s[threadIdx.x + o];
            __syncthreads();
        }
        if (threadIdx.x == 0) {
            out[0] = (float)(red_s[0] / (double)N_);
            g_ticket = 0;
        }
    }
}

extern "C" void kernel_launch(void* const* d_in, const int* in_sizes, int n_in,
                              void* d_out, int out_size) {
    const float* emb    = (const float*)d_in[0];  // output_embedding [N, D] f32
    const float* p      = (const float*)d_in[1];  // input_similarity [N, K] f32
    const int*   anchor = (const int*)d_in[2];    // anchor_idx [N, K] int32
    float* out = (float*)d_out;                   // [0]=loss, [1..]=q row-major

    snl_prep_kernel<<<NBLOCKS_, THREADS_>>>(emb);
    snl_main_kernel<<<NBLOCKS_, THREADS_>>>(emb, p, anchor, out);
}